// round 5
// baseline (speedup 1.0000x reference)
#include <cuda_runtime.h>
#include <math.h>
#include <stdint.h>

// ---------------- problem constants ----------------------------------------
#define B_    16
#define M_    32
#define NC_   80
#define RMAX  16
#define N0_   6400
#define N1_   1600
#define N2_   400
#define NTOT  8400
#define NT4   2100      // NTOT/4
#define CCH   144
#define TOPK_ 10
#define EPS_  1e-9f
#define MAXC  512
#define LCAP  512       // fg-list capacity per image (true max 320)
#define RBLK  2         // resolve blocks per image (2*256 = 512 >= LCAP)
#define RTOT  (RBLK * B_)
#define DBLK  9         // blocks per role per image (9*256 >= 2100)
#define NROLE 8

// ---------------- scratch ---------------------------------------------------
__device__ float4   g_pred[B_ * NTOT];
__device__ unsigned g_mask[B_ * NTOT];
__device__ float    g_mmax[B_ * M_];
__device__ int      g_cnt[B_];
__device__ int      g_list[B_][LCAP];
__device__ double   g_acc[8];   // 0 bce_base, 1 ts_sum, 2 box, 3 dfl, 4 bce_tgt
__device__ unsigned g_done;

// ---------------- helpers ---------------------------------------------------
struct AInfo { const float* base; int hw; float s, ax, ay; };

__device__ __forceinline__ AInfo ainfo(int b, int n, const float* p0,
                                       const float* p1, const float* p2) {
    AInfo a;
    if (n < N0_) {
        int w = n % 80, h = n / 80;
        a.hw = N0_; a.s = 8.f;
        a.ax = (w + 0.5f) * 8.f; a.ay = (h + 0.5f) * 8.f;
        a.base = p0 + (size_t)b * CCH * N0_ + n;
    } else if (n < N0_ + N1_) {
        int q = n - N0_; int w = q % 40, h = q / 40;
        a.hw = N1_; a.s = 16.f;
        a.ax = (w + 0.5f) * 16.f; a.ay = (h + 0.5f) * 16.f;
        a.base = p1 + (size_t)b * CCH * N1_ + q;
    } else {
        int q = n - N0_ - N1_; int w = q % 20, h = q / 20;
        a.hw = N2_; a.s = 32.f;
        a.ax = (w + 0.5f) * 32.f; a.ay = (h + 0.5f) * 32.f;
        a.base = p2 + (size_t)b * CCH * N2_ + q;
    }
    return a;
}

__device__ __forceinline__ float iou_plain(float x1, float y1, float x2, float y2,
                                           float a1,
                                           float gx1, float gy1, float gx2, float gy2) {
    float iw = fmaxf(fminf(x2, gx2) - fmaxf(x1, gx1), 0.f);
    float ih = fmaxf(fminf(y2, gy2) - fmaxf(y1, gy1), 0.f);
    float inter = iw * ih;
    float w2 = fmaxf(gx2 - gx1, 0.f), h2 = fmaxf(gy2 - gy1, 0.f);
    float uni = a1 + w2 * h2 - inter + 1e-7f;
    return inter / uni;
}

__device__ __forceinline__ float pow6(float x) { float t = x * x; return t * t * t; }

__device__ __forceinline__ float align_metric(float zlogit, float iou) {
    float sig = 1.f / (1.f + __expf(-zlogit));
    return sqrtf(sig) * pow6(fmaxf(iou, 0.f));
}

__device__ __forceinline__ float block_sum(float v) {
    __shared__ float sh[8];
    __syncthreads();
    int lane = threadIdx.x & 31, wid = threadIdx.x >> 5;
    #pragma unroll
    for (int o = 16; o > 0; o >>= 1) v += __shfl_down_sync(0xffffffffu, v, o);
    if (lane == 0) sh[wid] = v;
    __syncthreads();
    v = (threadIdx.x < 8) ? sh[threadIdx.x] : 0.f;
    if (wid == 0) {
        #pragma unroll
        for (int o = 4; o > 0; o >>= 1) v += __shfl_down_sync(0xffffffffu, v, o);
    }
    return v;
}

__device__ __forceinline__ float4 block_sum4(float4 v) {
    __shared__ float sh4[8][4];
    __syncthreads();
    int lane = threadIdx.x & 31, wid = threadIdx.x >> 5;
    #pragma unroll
    for (int o = 16; o > 0; o >>= 1) {
        v.x += __shfl_down_sync(0xffffffffu, v.x, o);
        v.y += __shfl_down_sync(0xffffffffu, v.y, o);
        v.z += __shfl_down_sync(0xffffffffu, v.z, o);
        v.w += __shfl_down_sync(0xffffffffu, v.w, o);
    }
    if (lane == 0) { sh4[wid][0] = v.x; sh4[wid][1] = v.y;
                     sh4[wid][2] = v.z; sh4[wid][3] = v.w; }
    __syncthreads();
    float4 u = make_float4(0.f, 0.f, 0.f, 0.f);
    if (wid == 0) {
        if (lane < 8) { u.x = sh4[lane][0]; u.y = sh4[lane][1];
                        u.z = sh4[lane][2]; u.w = sh4[lane][3]; }
        #pragma unroll
        for (int o = 4; o > 0; o >>= 1) {
            u.x += __shfl_down_sync(0xffffffffu, u.x, o);
            u.y += __shfl_down_sync(0xffffffffu, u.y, o);
            u.z += __shfl_down_sync(0xffffffffu, u.z, o);
            u.w += __shfl_down_sync(0xffffffffu, u.w, o);
        }
    }
    return u;
}

// one DFL side for 4 anchors: two-group online softmax (8 float4 live)
__device__ __forceinline__ void dfl_side(const float4* zp, size_t hw4, float s,
                                         float dout[4]) {
    float4 z[8];
    #pragma unroll
    for (int j = 0; j < 8; j++) z[j] = zp[(size_t)j * hw4];
    float4 mxA = z[0];
    #pragma unroll
    for (int j = 1; j < 8; j++) {
        mxA.x = fmaxf(mxA.x, z[j].x); mxA.y = fmaxf(mxA.y, z[j].y);
        mxA.z = fmaxf(mxA.z, z[j].z); mxA.w = fmaxf(mxA.w, z[j].w);
    }
    float4 seA = make_float4(0.f,0.f,0.f,0.f), swA = seA;
    #pragma unroll
    for (int j = 0; j < 8; j++) {
        float fj = (float)j;
        float e;
        e = __expf(z[j].x - mxA.x); seA.x += e; swA.x += e * fj;
        e = __expf(z[j].y - mxA.y); seA.y += e; swA.y += e * fj;
        e = __expf(z[j].z - mxA.z); seA.z += e; swA.z += e * fj;
        e = __expf(z[j].w - mxA.w); seA.w += e; swA.w += e * fj;
    }
    #pragma unroll
    for (int j = 0; j < 8; j++) z[j] = zp[(size_t)(j + 8) * hw4];
    float4 mxB = z[0];
    #pragma unroll
    for (int j = 1; j < 8; j++) {
        mxB.x = fmaxf(mxB.x, z[j].x); mxB.y = fmaxf(mxB.y, z[j].y);
        mxB.z = fmaxf(mxB.z, z[j].z); mxB.w = fmaxf(mxB.w, z[j].w);
    }
    float4 seB = make_float4(0.f,0.f,0.f,0.f), swB = seB;
    #pragma unroll
    for (int j = 0; j < 8; j++) {
        float fj = (float)(j + 8);
        float e;
        e = __expf(z[j].x - mxB.x); seB.x += e; swB.x += e * fj;
        e = __expf(z[j].y - mxB.y); seB.y += e; swB.y += e * fj;
        e = __expf(z[j].z - mxB.z); seB.z += e; swB.z += e * fj;
        e = __expf(z[j].w - mxB.w); seB.w += e; swB.w += e * fj;
    }
    #pragma unroll
    for (int k = 0; k < 4; k++) {
        float ma = ((const float*)&mxA)[k], mb = ((const float*)&mxB)[k];
        float m = fmaxf(ma, mb);
        float fa = __expf(ma - m), fb = __expf(mb - m);
        float se = ((const float*)&seA)[k] * fa + ((const float*)&seB)[k] * fb;
        float sw = ((const float*)&swA)[k] * fa + ((const float*)&swB)[k] * fb;
        dout[k] = sw / se * s;
    }
}

// ---------------- kernel 1: decode + bce, 8-way role split ------------------
// roles 0..3: DFL side = role (role 0 also zeroes mask + counters)
// roles 4..7: BCE channels 64 + (role-4)*20 .. +20
__global__ __launch_bounds__(256) void k_decode(
    const float* __restrict__ p0, const float* __restrict__ p1,
    const float* __restrict__ p2) {
    int b = blockIdx.y;
    int role = blockIdx.x / DBLK;
    int t = (blockIdx.x - role * DBLK) * 256 + threadIdx.x;   // 0 .. 2303
    if (role == 0 && blockIdx.x == 0 && threadIdx.x == 0) g_cnt[b] = 0;
    float bce = 0.f;
    if (t < NT4) {
        const float* lp; int W, hw, q0, nbase; float s;
        if (t < 1600)      { lp = p0; W = 80; hw = N0_; s = 8.f;  q0 = 4 * t;        nbase = 0; }
        else if (t < 2000) { lp = p1; W = 40; hw = N1_; s = 16.f; q0 = 4 * t - 6400; nbase = N0_; }
        else               { lp = p2; W = 20; hw = N2_; s = 32.f; q0 = 4 * t - 8000; nbase = N0_ + N1_; }
        size_t hw4 = (size_t)(hw >> 2);
        const float4* base4 = (const float4*)(lp + (size_t)b * CCH * hw + q0);
        size_t pidx = (size_t)b * NTOT + nbase + q0;

        if (role < 4) {
            int side = role;
            float d[4];
            dfl_side(base4 + (size_t)side * RMAX * hw4, hw4, s, d);
            float* pr = (float*)&g_pred[pidx];
            #pragma unroll
            for (int k = 0; k < 4; k++) {
                int q = q0 + k;
                float coord = (side & 1) ? ((q / W) + 0.5f) * s
                                         : ((q % W) + 0.5f) * s;
                pr[4 * k + side] = (side < 2) ? coord - d[k] : coord + d[k];
            }
            if (role == 0)
                ((uint4*)g_mask)[pidx >> 2] = make_uint4(0u, 0u, 0u, 0u);
        } else {
            const float4* cb4 = base4 + (size_t)(64 + (role - 4) * 20) * hw4;
            float4 acc = make_float4(0.f, 0.f, 0.f, 0.f);
            #pragma unroll 1
            for (int g = 0; g < 2; g++) {
                float4 prod = make_float4(1.f, 1.f, 1.f, 1.f);
                #pragma unroll
                for (int j = 0; j < 10; j++) {
                    float4 zz = cb4[(size_t)(g * 10 + j) * hw4];
                    acc.x += fmaxf(zz.x, 0.f); acc.y += fmaxf(zz.y, 0.f);
                    acc.z += fmaxf(zz.z, 0.f); acc.w += fmaxf(zz.w, 0.f);
                    prod.x *= 1.f + __expf(-fabsf(zz.x));
                    prod.y *= 1.f + __expf(-fabsf(zz.y));
                    prod.z *= 1.f + __expf(-fabsf(zz.z));
                    prod.w *= 1.f + __expf(-fabsf(zz.w));
                }
                acc.x += __logf(prod.x); acc.y += __logf(prod.y);
                acc.z += __logf(prod.z); acc.w += __logf(prod.w);
            }
            bce = (acc.x + acc.y) + (acc.z + acc.w);
        }
    }
    if (role >= 4) {
        float tot = block_sum(bce);
        if (threadIdx.x == 0 && tot != 0.f) atomicAdd(&g_acc[0], (double)tot);
    }
}

// ---------------- kernel 2: GT-centric assign + fg-list compaction ----------
__global__ __launch_bounds__(128) void k_assign(
    const float* __restrict__ p0, const float* __restrict__ p1,
    const float* __restrict__ p2, const float* __restrict__ gtb,
    const int* __restrict__ glw) {
    int m = blockIdx.x, b = blockIdx.y;
    int tid = threadIdx.x;
    __shared__ unsigned long long skey[MAXC];
    __shared__ unsigned long long swarp[4];
    __shared__ unsigned long long swin;
    __shared__ int scount, slab;
    __shared__ float sbox[4];

    if (tid < 32) {
        int nz = glw[2 * tid + 1];
        unsigned bal = __ballot_sync(0xffffffffu, nz != 0);
        if (tid == 0) {
            int is64 = (bal == 0);
            int idx = b * M_ + m;
            int lab = is64 ? glw[2 * idx] : glw[idx];
            slab = min(max(lab, 0), NC_ - 1);
            scount = 0;
            const float* g = gtb + (size_t)idx * 4;
            sbox[0] = g[0]; sbox[1] = g[1]; sbox[2] = g[2]; sbox[3] = g[3];
            g_mmax[idx] = EPS_;
        }
    }
    for (int i = tid; i < MAXC; i += 128) skey[i] = 0ull;
    __syncthreads();

    float gx1 = sbox[0], gy1 = sbox[1], gx2 = sbox[2], gy2 = sbox[3];
    float w2 = fmaxf(gx2 - gx1, 0.f), h2 = fmaxf(gy2 - gy1, 0.f);
    float garea = w2 * h2;
    int lab = slab;

    const float* lp[3] = { p0, p1, p2 };
    const int   lW[3] = { 80, 40, 20 };
    const int   lhw[3] = { N0_, N1_, N2_ };
    const float ls[3] = { 8.f, 16.f, 32.f };
    const int   lbase[3] = { 0, N0_, N0_ + N1_ };

    #pragma unroll
    for (int l = 0; l < 3; l++) {
        float s = ls[l]; int W = lW[l];
        int xlo = max(0, (int)floorf(gx1 / s - 0.5f));
        int xhi = min(W - 1, (int)ceilf(gx2 / s - 0.5f));
        int ylo = max(0, (int)floorf(gy1 / s - 0.5f));
        int yhi = min(W - 1, (int)ceilf(gy2 / s - 0.5f));
        int nx = xhi - xlo + 1, ny = yhi - ylo + 1;
        if (nx <= 0 || ny <= 0) continue;
        int cells = nx * ny;
        const float* clsp = lp[l] + (size_t)b * CCH * lhw[l] + (size_t)(64 + lab) * lhw[l];
        for (int idx = tid; idx < cells; idx += 128) {
            int w = xlo + idx % nx, h = ylo + idx / nx;
            float ax = (w + 0.5f) * s, ay = (h + 0.5f) * s;
            if (ax - gx1 > 0.f && ay - gy1 > 0.f && gx2 - ax > 0.f && gy2 - ay > 0.f) {
                int pos = h * W + w;
                int n = lbase[l] + pos;
                float4 pb = g_pred[(size_t)b * NTOT + n];
                float a1 = fmaxf(pb.z - pb.x, 0.f) * fmaxf(pb.w - pb.y, 0.f);
                float iw = fmaxf(fminf(pb.z, gx2) - fmaxf(pb.x, gx1), 0.f);
                float ih = fmaxf(fminf(pb.w, gy2) - fmaxf(pb.y, gy1), 0.f);
                float inter = iw * ih;
                float iou = inter / (a1 + garea - inter + 1e-7f);
                float al = align_metric(clsp[pos], iou);
                int slot = atomicAdd(&scount, 1);
                if (slot < MAXC)
                    skey[slot] = ((unsigned long long)__float_as_uint(al) << 32)
                               | (unsigned)(NTOT - n);
            }
        }
    }
    __syncthreads();
    int cnt = min(scount, MAXC);
    int lane = tid & 31, wid = tid >> 5;

    for (int k = 0; k < TOPK_; k++) {
        unsigned long long loc = 0ull;
        for (int i = tid; i < cnt; i += 128) loc = max(loc, skey[i]);
        #pragma unroll
        for (int o = 16; o > 0; o >>= 1)
            loc = max(loc, __shfl_down_sync(0xffffffffu, loc, o));
        if (lane == 0) swarp[wid] = loc;
        __syncthreads();
        if (tid == 0) {
            unsigned long long w0 = max(max(swarp[0], swarp[1]),
                                        max(swarp[2], swarp[3]));
            swin = w0;
            if (w0 != 0ull) {
                if (k == 0)
                    g_mmax[b * M_ + m] =
                        fmaxf(__uint_as_float((unsigned)(w0 >> 32)), EPS_);
                int n = NTOT - (int)(unsigned)(w0 & 0xffffffffu);
                unsigned old = atomicOr(&g_mask[b * NTOT + n], 1u << m);
                if (old == 0u) {
                    int li = atomicAdd(&g_cnt[b], 1);
                    if (li < LCAP) g_list[b][li] = n;
                }
            }
        }
        __syncthreads();
        unsigned long long win = swin;
        if (win == 0ull) break;
        for (int i = tid; i < cnt; i += 128)
            if (skey[i] == win) skey[i] = 0ull;
        __syncthreads();
    }
}

// ---------------- kernel 3: resolve over compacted fg list ------------------
__global__ __launch_bounds__(256) void k_resolve(
    const float* __restrict__ p0, const float* __restrict__ p1,
    const float* __restrict__ p2, const float* __restrict__ gtb,
    const int* __restrict__ glw, float* __restrict__ out) {
    int b = blockIdx.y;
    int i = blockIdx.x * 256 + threadIdx.x;
    __shared__ float sg[M_][4];
    __shared__ int   sl[M_];
    __shared__ float smm[M_];
    __shared__ int   s64;
    if (threadIdx.x < 32) {
        int nz = glw[2 * threadIdx.x + 1];
        unsigned bal = __ballot_sync(0xffffffffu, nz != 0);
        if (threadIdx.x == 0) s64 = (bal == 0);
    }
    __syncthreads();
    if (threadIdx.x < M_) {
        int m = threadIdx.x;
        int idx = b * M_ + m;
        const float* g = gtb + (size_t)idx * 4;
        sg[m][0] = g[0]; sg[m][1] = g[1]; sg[m][2] = g[2]; sg[m][3] = g[3];
        int lab = s64 ? glw[2 * idx] : glw[idx];
        sl[m] = min(max(lab, 0), NC_ - 1);
        smm[m] = g_mmax[idx];
    }
    __syncthreads();

    float4 part = make_float4(0.f, 0.f, 0.f, 0.f);  // ts, box, dfl, bce_tgt
    int cnt = min(g_cnt[b], LCAP);
    if (i < cnt) {
        int n = g_list[b][i];
        unsigned mk = g_mask[b * NTOT + n];
        {
            float4 pb = g_pred[(size_t)b * NTOT + n];
            float x1 = pb.x, y1 = pb.y, x2 = pb.z, y2 = pb.w;
            float w1 = fmaxf(x2 - x1, 0.f), h1 = fmaxf(y2 - y1, 0.f);
            float a1 = w1 * h1;
            float best = -3.f; int bi = 0;
            unsigned mm = mk;
            while (mm) {
                int m = __ffs(mm) - 1; mm &= mm - 1;
                float v = iou_plain(x1, y1, x2, y2, a1,
                                    sg[m][0], sg[m][1], sg[m][2], sg[m][3]);
                if (v > best) { best = v; bi = m; }
            }
            AInfo a = ainfo(b, n, p0, p1, p2);
            float zl = a.base[(size_t)(64 + sl[bi]) * a.hw];
            float alv = align_metric(zl, best);
            float score = fminf(fmaxf(alv / smm[bi] * best, 0.f), 1.f);
            part.x = score;
            if (score > 0.f) {
                float gx1 = sg[bi][0], gy1 = sg[bi][1];
                float gx2 = sg[bi][2], gy2 = sg[bi][3];
                float iw = fmaxf(fminf(x2, gx2) - fmaxf(x1, gx1), 0.f);
                float ih = fmaxf(fminf(y2, gy2) - fmaxf(y1, gy1), 0.f);
                float inter = iw * ih;
                float w2 = fmaxf(gx2 - gx1, 0.f), h2 = fmaxf(gy2 - gy1, 0.f);
                float uni = a1 + w2 * h2 - inter + 1e-7f;
                float iou = inter / uni;
                float dcx = (gx1 + gx2) * 0.5f - (x1 + x2) * 0.5f;
                float dcy = (gy1 + gy2) * 0.5f - (y1 + y2) * 0.5f;
                float rho2 = dcx * dcx + dcy * dcy;
                float cw = fmaxf(x2, gx2) - fminf(x1, gx1);
                float chh = fmaxf(y2, gy2) - fminf(y1, gy1);
                float c2 = cw * cw + chh * chh + 1e-7f;
                const float k4pi2 = 0.40528473456935108577f;
                float dv = atanf(w2 / (h2 + 1e-7f)) - atanf(w1 / (h1 + 1e-7f));
                float v = k4pi2 * dv * dv;
                float alpha = v / (1.f - iou + v + 1e-7f);
                float ciou = iou - (rho2 / c2 + alpha * v);
                part.y = (1.f - ciou) * score;
                float inv = 1.f / a.s;
                float tgt[4] = { (a.ax - gx1) * inv, (a.ay - gy1) * inv,
                                 (gx2 - a.ax) * inv, (gy2 - a.ay) * inv };
                float dfl = 0.f;
                #pragma unroll
                for (int sd = 0; sd < 4; sd++) {
                    float z[RMAX]; float mx = -3.4e38f;
                    #pragma unroll
                    for (int j = 0; j < RMAX; j++) {
                        z[j] = a.base[(size_t)(sd * RMAX + j) * a.hw];
                        mx = fmaxf(mx, z[j]);
                    }
                    float se = 0.f;
                    #pragma unroll
                    for (int j = 0; j < RMAX; j++) se += __expf(z[j] - mx);
                    float ls = mx + __logf(se);
                    float t = fminf(fmaxf(tgt[sd], 0.f), 15.f);
                    int L = (int)floorf(t);
                    int R = min(L + 1, RMAX - 1);
                    float wl = (R == L) ? 1.f : ((float)R - t);
                    float wr = (R == L) ? 0.f : (t - (float)L);
                    dfl += (ls - z[L]) * wl + (ls - z[R]) * wr;
                }
                part.z = dfl * score;
                part.w = zl * score;
            }
        }
    }
    float4 r = block_sum4(part);
    if (threadIdx.x == 0) {
        if (r.x != 0.f) atomicAdd(&g_acc[1], (double)r.x);
        if (r.y != 0.f) atomicAdd(&g_acc[2], (double)r.y);
        if (r.z != 0.f) atomicAdd(&g_acc[3], (double)r.z);
        if (r.w != 0.f) atomicAdd(&g_acc[4], (double)r.w);
        __threadfence();
        unsigned c = atomicAdd(&g_done, 1u);
        if (c == RTOT - 1) {
            double a0 = atomicAdd(&g_acc[0], 0.0);
            double a1 = atomicAdd(&g_acc[1], 0.0);
            double a2 = atomicAdd(&g_acc[2], 0.0);
            double a3 = atomicAdd(&g_acc[3], 0.0);
            double a4 = atomicAdd(&g_acc[4], 0.0);
            double tsum = a1 < 1.0 ? 1.0 : a1;
            out[0] = (float)((7.5 * a2 + 0.5 * (a0 - a4) + 1.5 * a3) / tsum);
            #pragma unroll
            for (int i2 = 0; i2 < 8; i2++) g_acc[i2] = 0.0;
            g_done = 0u;
        }
    }
}

// ---------------- launch -----------------------------------------------------
extern "C" void kernel_launch(void* const* d_in, const int* in_sizes, int n_in,
                              void* d_out, int out_size) {
    const float* p0  = (const float*)d_in[0];
    const float* p1  = (const float*)d_in[1];
    const float* p2  = (const float*)d_in[2];
    const float* gtb = (const float*)d_in[3];
    const int*   glw = (const int*)d_in[4];
    (void)in_sizes; (void)n_in; (void)out_size;

    k_decode<<<dim3(NROLE * DBLK, B_), 256>>>(p0, p1, p2);
    k_assign<<<dim3(M_, B_), 128>>>(p0, p1, p2, gtb, glw);
    k_resolve<<<dim3(RBLK, B_), 256>>>(p0, p1, p2, gtb, glw, (float*)d_out);
}

// round 6
// speedup vs baseline: 1.3406x; 1.3406x over previous
#include <cuda_runtime.h>
#include <math.h>
#include <stdint.h>

// ---------------- problem constants ----------------------------------------
#define B_    16
#define M_    32
#define NC_   80
#define RMAX  16
#define N0_   6400
#define N1_   1600
#define N2_   400
#define NTOT  8400
#define NT4   2100      // NTOT/4
#define CCH   144
#define TOPK_ 10
#define EPS_  1e-9f
#define MAXC  512
#define LCAP  512       // fg-list capacity per image (true max 320)
#define RBLK  4         // resolve blocks per image (4*128 = 512 >= LCAP)
#define RTOT  (RBLK * B_)
#define DBLK  9         // blocks per role per image (9*256 >= 2100)

// ---------------- scratch ---------------------------------------------------
__device__ float4   g_pred[B_ * NTOT];
__device__ unsigned g_mask[B_ * NTOT];
__device__ float    g_mmax[B_ * M_];
__device__ int      g_cnt[B_];
__device__ int      g_list[B_][LCAP];
__device__ double   g_acc[8];   // 0 bce_base, 1 ts_sum, 2 box, 3 dfl, 4 bce_tgt
__device__ unsigned g_done;

// ---------------- helpers ---------------------------------------------------
struct AInfo { const float* base; int hw; float s, ax, ay; };

__device__ __forceinline__ AInfo ainfo(int b, int n, const float* p0,
                                       const float* p1, const float* p2) {
    AInfo a;
    if (n < N0_) {
        int w = n % 80, h = n / 80;
        a.hw = N0_; a.s = 8.f;
        a.ax = (w + 0.5f) * 8.f; a.ay = (h + 0.5f) * 8.f;
        a.base = p0 + (size_t)b * CCH * N0_ + n;
    } else if (n < N0_ + N1_) {
        int q = n - N0_; int w = q % 40, h = q / 40;
        a.hw = N1_; a.s = 16.f;
        a.ax = (w + 0.5f) * 16.f; a.ay = (h + 0.5f) * 16.f;
        a.base = p1 + (size_t)b * CCH * N1_ + q;
    } else {
        int q = n - N0_ - N1_; int w = q % 20, h = q / 20;
        a.hw = N2_; a.s = 32.f;
        a.ax = (w + 0.5f) * 32.f; a.ay = (h + 0.5f) * 32.f;
        a.base = p2 + (size_t)b * CCH * N2_ + q;
    }
    return a;
}

__device__ __forceinline__ float iou_plain(float x1, float y1, float x2, float y2,
                                           float a1,
                                           float gx1, float gy1, float gx2, float gy2) {
    float iw = fmaxf(fminf(x2, gx2) - fmaxf(x1, gx1), 0.f);
    float ih = fmaxf(fminf(y2, gy2) - fmaxf(y1, gy1), 0.f);
    float inter = iw * ih;
    float w2 = fmaxf(gx2 - gx1, 0.f), h2 = fmaxf(gy2 - gy1, 0.f);
    float uni = a1 + w2 * h2 - inter + 1e-7f;
    return inter / uni;
}

__device__ __forceinline__ float pow6(float x) { float t = x * x; return t * t * t; }

__device__ __forceinline__ float align_metric(float zlogit, float iou) {
    float sig = 1.f / (1.f + __expf(-zlogit));
    return sqrtf(sig) * pow6(fmaxf(iou, 0.f));
}

__device__ __forceinline__ float block_sum(float v) {       // 256 threads
    __shared__ float sh[8];
    __syncthreads();
    int lane = threadIdx.x & 31, wid = threadIdx.x >> 5;
    #pragma unroll
    for (int o = 16; o > 0; o >>= 1) v += __shfl_down_sync(0xffffffffu, v, o);
    if (lane == 0) sh[wid] = v;
    __syncthreads();
    v = (threadIdx.x < 8) ? sh[threadIdx.x] : 0.f;
    if (wid == 0) {
        #pragma unroll
        for (int o = 4; o > 0; o >>= 1) v += __shfl_down_sync(0xffffffffu, v, o);
    }
    return v;
}

__device__ __forceinline__ float4 block_sum4_128(float4 v) { // 128 threads
    __shared__ float sh4[4][4];
    __syncthreads();
    int lane = threadIdx.x & 31, wid = threadIdx.x >> 5;
    #pragma unroll
    for (int o = 16; o > 0; o >>= 1) {
        v.x += __shfl_down_sync(0xffffffffu, v.x, o);
        v.y += __shfl_down_sync(0xffffffffu, v.y, o);
        v.z += __shfl_down_sync(0xffffffffu, v.z, o);
        v.w += __shfl_down_sync(0xffffffffu, v.w, o);
    }
    if (lane == 0) { sh4[wid][0] = v.x; sh4[wid][1] = v.y;
                     sh4[wid][2] = v.z; sh4[wid][3] = v.w; }
    __syncthreads();
    float4 u = make_float4(0.f, 0.f, 0.f, 0.f);
    if (wid == 0) {
        if (lane < 4) { u.x = sh4[lane][0]; u.y = sh4[lane][1];
                        u.z = sh4[lane][2]; u.w = sh4[lane][3]; }
        #pragma unroll
        for (int o = 2; o > 0; o >>= 1) {
            u.x += __shfl_down_sync(0xffffffffu, u.x, o);
            u.y += __shfl_down_sync(0xffffffffu, u.y, o);
            u.z += __shfl_down_sync(0xffffffffu, u.z, o);
            u.w += __shfl_down_sync(0xffffffffu, u.w, o);
        }
    }
    return u;
}

// one DFL side for 4 anchors: two-group online softmax
__device__ __forceinline__ void dfl_side(const float4* zp, size_t hw4, float s,
                                         float dout[4]) {
    float4 z[8];
    #pragma unroll
    for (int j = 0; j < 8; j++) z[j] = zp[(size_t)j * hw4];
    float4 mxA = z[0];
    #pragma unroll
    for (int j = 1; j < 8; j++) {
        mxA.x = fmaxf(mxA.x, z[j].x); mxA.y = fmaxf(mxA.y, z[j].y);
        mxA.z = fmaxf(mxA.z, z[j].z); mxA.w = fmaxf(mxA.w, z[j].w);
    }
    float4 seA = make_float4(0.f,0.f,0.f,0.f), swA = seA;
    #pragma unroll
    for (int j = 0; j < 8; j++) {
        float fj = (float)j;
        float e;
        e = __expf(z[j].x - mxA.x); seA.x += e; swA.x += e * fj;
        e = __expf(z[j].y - mxA.y); seA.y += e; swA.y += e * fj;
        e = __expf(z[j].z - mxA.z); seA.z += e; swA.z += e * fj;
        e = __expf(z[j].w - mxA.w); seA.w += e; swA.w += e * fj;
    }
    #pragma unroll
    for (int j = 0; j < 8; j++) z[j] = zp[(size_t)(j + 8) * hw4];
    float4 mxB = z[0];
    #pragma unroll
    for (int j = 1; j < 8; j++) {
        mxB.x = fmaxf(mxB.x, z[j].x); mxB.y = fmaxf(mxB.y, z[j].y);
        mxB.z = fmaxf(mxB.z, z[j].z); mxB.w = fmaxf(mxB.w, z[j].w);
    }
    float4 seB = make_float4(0.f,0.f,0.f,0.f), swB = seB;
    #pragma unroll
    for (int j = 0; j < 8; j++) {
        float fj = (float)(j + 8);
        float e;
        e = __expf(z[j].x - mxB.x); seB.x += e; swB.x += e * fj;
        e = __expf(z[j].y - mxB.y); seB.y += e; swB.y += e * fj;
        e = __expf(z[j].z - mxB.z); seB.z += e; swB.z += e * fj;
        e = __expf(z[j].w - mxB.w); seB.w += e; swB.w += e * fj;
    }
    #pragma unroll
    for (int k = 0; k < 4; k++) {
        float ma = ((const float*)&mxA)[k], mb = ((const float*)&mxB)[k];
        float m = fmaxf(ma, mb);
        float fa = __expf(ma - m), fb = __expf(mb - m);
        float se = ((const float*)&seA)[k] * fa + ((const float*)&seB)[k] * fb;
        float sw = ((const float*)&swA)[k] * fa + ((const float*)&swB)[k] * fb;
        dout[k] = sw / se * s;
    }
}

// ---------------- kernel 1: decode + bce (R4 structure, 4 roles) ------------
// roles: 0 = DFL sides 0,1 (+ mask zero + cnt zero)  1 = DFL sides 2,3
//        2 = BCE ch 64..103                          3 = BCE ch 104..143
__global__ __launch_bounds__(256) void k_decode(
    const float* __restrict__ p0, const float* __restrict__ p1,
    const float* __restrict__ p2) {
    int b = blockIdx.y;
    int role = blockIdx.x / DBLK;
    int t = (blockIdx.x - role * DBLK) * 256 + threadIdx.x;   // 0 .. 2303
    if (blockIdx.x == 0 && threadIdx.x == 0) g_cnt[b] = 0;
    float bce = 0.f;
    if (t < NT4) {
        const float* lp; int W, hw, q0, nbase; float s;
        if (t < 1600)      { lp = p0; W = 80; hw = N0_; s = 8.f;  q0 = 4 * t;        nbase = 0; }
        else if (t < 2000) { lp = p1; W = 40; hw = N1_; s = 16.f; q0 = 4 * t - 6400; nbase = N0_; }
        else               { lp = p2; W = 20; hw = N2_; s = 32.f; q0 = 4 * t - 8000; nbase = N0_ + N1_; }
        size_t hw4 = (size_t)(hw >> 2);
        const float4* base4 = (const float4*)(lp + (size_t)b * CCH * hw + q0);
        size_t pidx = (size_t)b * NTOT + nbase + q0;

        if (role < 2) {
            float d0[4], d1[4];
            dfl_side(base4 + (size_t)(role * 2 + 0) * RMAX * hw4, hw4, s, d0);
            dfl_side(base4 + (size_t)(role * 2 + 1) * RMAX * hw4, hw4, s, d1);
            float2* pr2 = (float2*)&g_pred[pidx];
            #pragma unroll
            for (int k = 0; k < 4; k++) {
                int q = q0 + k;
                float ax = ((q % W) + 0.5f) * s, ay = ((q / W) + 0.5f) * s;
                if (role == 0) pr2[2 * k]     = make_float2(ax - d0[k], ay - d1[k]);
                else           pr2[2 * k + 1] = make_float2(ax + d0[k], ay + d1[k]);
            }
            if (role == 0)
                ((uint4*)g_mask)[pidx >> 2] = make_uint4(0u, 0u, 0u, 0u);
        } else {
            const float4* cb4 = base4 + (size_t)(64 + (role - 2) * 40) * hw4;
            float4 acc = make_float4(0.f, 0.f, 0.f, 0.f);
            #pragma unroll 1
            for (int g = 0; g < 5; g++) {
                float4 prod = make_float4(1.f, 1.f, 1.f, 1.f);
                #pragma unroll
                for (int j = 0; j < 8; j++) {
                    float4 zz = cb4[(size_t)(g * 8 + j) * hw4];
                    acc.x += fmaxf(zz.x, 0.f); acc.y += fmaxf(zz.y, 0.f);
                    acc.z += fmaxf(zz.z, 0.f); acc.w += fmaxf(zz.w, 0.f);
                    prod.x *= 1.f + __expf(-fabsf(zz.x));
                    prod.y *= 1.f + __expf(-fabsf(zz.y));
                    prod.z *= 1.f + __expf(-fabsf(zz.z));
                    prod.w *= 1.f + __expf(-fabsf(zz.w));
                }
                acc.x += __logf(prod.x); acc.y += __logf(prod.y);
                acc.z += __logf(prod.z); acc.w += __logf(prod.w);
            }
            bce = (acc.x + acc.y) + (acc.z + acc.w);
        }
    }
    if (role >= 2) {
        float tot = block_sum(bce);
        if (threadIdx.x == 0 && tot != 0.f) atomicAdd(&g_acc[0], (double)tot);
    }
}

// ---------------- kernel 2: GT-centric assign (parallel winner commit) ------
__global__ __launch_bounds__(128) void k_assign(
    const float* __restrict__ p0, const float* __restrict__ p1,
    const float* __restrict__ p2, const float* __restrict__ gtb,
    const int* __restrict__ glw) {
    int m = blockIdx.x, b = blockIdx.y;
    int tid = threadIdx.x;
    __shared__ unsigned long long skey[MAXC];
    __shared__ unsigned long long swarp[4];
    __shared__ unsigned long long swink[TOPK_];
    __shared__ int scount, slab;
    __shared__ float sbox[4];

    if (tid < 32) {
        int nz = glw[2 * tid + 1];
        unsigned bal = __ballot_sync(0xffffffffu, nz != 0);
        if (tid == 0) {
            int is64 = (bal == 0);
            int idx = b * M_ + m;
            int lab = is64 ? glw[2 * idx] : glw[idx];
            slab = min(max(lab, 0), NC_ - 1);
            scount = 0;
            const float* g = gtb + (size_t)idx * 4;
            sbox[0] = g[0]; sbox[1] = g[1]; sbox[2] = g[2]; sbox[3] = g[3];
        }
    }
    for (int i = tid; i < MAXC; i += 128) skey[i] = 0ull;
    __syncthreads();

    float gx1 = sbox[0], gy1 = sbox[1], gx2 = sbox[2], gy2 = sbox[3];
    float w2 = fmaxf(gx2 - gx1, 0.f), h2 = fmaxf(gy2 - gy1, 0.f);
    float garea = w2 * h2;
    int lab = slab;

    const float* lp[3] = { p0, p1, p2 };
    const int   lW[3] = { 80, 40, 20 };
    const int   lhw[3] = { N0_, N1_, N2_ };
    const float ls[3] = { 8.f, 16.f, 32.f };
    const int   lbase[3] = { 0, N0_, N0_ + N1_ };

    #pragma unroll
    for (int l = 0; l < 3; l++) {
        float s = ls[l]; int W = lW[l];
        int xlo = max(0, (int)floorf(gx1 / s - 0.5f));
        int xhi = min(W - 1, (int)ceilf(gx2 / s - 0.5f));
        int ylo = max(0, (int)floorf(gy1 / s - 0.5f));
        int yhi = min(W - 1, (int)ceilf(gy2 / s - 0.5f));
        int nx = xhi - xlo + 1, ny = yhi - ylo + 1;
        if (nx <= 0 || ny <= 0) continue;
        int cells = nx * ny;
        const float* clsp = lp[l] + (size_t)b * CCH * lhw[l] + (size_t)(64 + lab) * lhw[l];
        for (int idx = tid; idx < cells; idx += 128) {
            int w = xlo + idx % nx, h = ylo + idx / nx;
            float ax = (w + 0.5f) * s, ay = (h + 0.5f) * s;
            if (ax - gx1 > 0.f && ay - gy1 > 0.f && gx2 - ax > 0.f && gy2 - ay > 0.f) {
                int pos = h * W + w;
                int n = lbase[l] + pos;
                float4 pb = g_pred[(size_t)b * NTOT + n];
                float a1 = fmaxf(pb.z - pb.x, 0.f) * fmaxf(pb.w - pb.y, 0.f);
                float iw = fmaxf(fminf(pb.z, gx2) - fmaxf(pb.x, gx1), 0.f);
                float ih = fmaxf(fminf(pb.w, gy2) - fmaxf(pb.y, gy1), 0.f);
                float inter = iw * ih;
                float iou = inter / (a1 + garea - inter + 1e-7f);
                float al = align_metric(clsp[pos], iou);
                int slot = atomicAdd(&scount, 1);
                if (slot < MAXC)
                    skey[slot] = ((unsigned long long)__float_as_uint(al) << 32)
                               | (unsigned)(NTOT - n);
            }
        }
    }
    __syncthreads();
    int cnt = min(scount, MAXC);
    int lane = tid & 31, wid = tid >> 5;

    for (int k = 0; k < TOPK_; k++) {
        unsigned long long loc = 0ull;
        for (int i = tid; i < cnt; i += 128) loc = max(loc, skey[i]);
        #pragma unroll
        for (int o = 16; o > 0; o >>= 1)
            loc = max(loc, __shfl_down_sync(0xffffffffu, loc, o));
        if (lane == 0) swarp[wid] = loc;
        __syncthreads();
        if (tid == 0) {
            swink[k] = max(max(swarp[0], swarp[1]), max(swarp[2], swarp[3]));
        }
        __syncthreads();
        unsigned long long win = swink[k];
        if (win == 0ull) {
            if (tid < TOPK_ && tid > k) swink[tid] = 0ull;  // clear remainder
            __syncthreads();
            break;
        }
        if (k < TOPK_ - 1) {
            for (int i = tid; i < cnt; i += 128)
                if (skey[i] == win) skey[i] = 0ull;
            __syncthreads();
        }
    }
    // parallel commit: lanes 0..9 issue atomics concurrently
    if (tid == 0)
        g_mmax[b * M_ + m] = (swink[0] != 0ull)
            ? fmaxf(__uint_as_float((unsigned)(swink[0] >> 32)), EPS_) : EPS_;
    if (tid < TOPK_) {
        unsigned long long w0 = swink[tid];
        if (w0 != 0ull) {
            int n = NTOT - (int)(unsigned)(w0 & 0xffffffffu);
            unsigned old = atomicOr(&g_mask[b * NTOT + n], 1u << m);
            if (old == 0u) {
                int li = atomicAdd(&g_cnt[b], 1);
                if (li < LCAP) g_list[b][li] = n;
            }
        }
    }
}

// ---------------- kernel 3: resolve over compacted fg list ------------------
__global__ __launch_bounds__(128) void k_resolve(
    const float* __restrict__ p0, const float* __restrict__ p1,
    const float* __restrict__ p2, const float* __restrict__ gtb,
    const int* __restrict__ glw, float* __restrict__ out) {
    int b = blockIdx.y;
    int i = blockIdx.x * 128 + threadIdx.x;
    __shared__ float sg[M_][4];
    __shared__ int   sl[M_];
    __shared__ float smm[M_];
    __shared__ int   s64;
    if (threadIdx.x < 32) {
        int nz = glw[2 * threadIdx.x + 1];
        unsigned bal = __ballot_sync(0xffffffffu, nz != 0);
        if (threadIdx.x == 0) s64 = (bal == 0);
    }
    __syncthreads();
    if (threadIdx.x < M_) {
        int m = threadIdx.x;
        int idx = b * M_ + m;
        const float* g = gtb + (size_t)idx * 4;
        sg[m][0] = g[0]; sg[m][1] = g[1]; sg[m][2] = g[2]; sg[m][3] = g[3];
        int lab = s64 ? glw[2 * idx] : glw[idx];
        sl[m] = min(max(lab, 0), NC_ - 1);
        smm[m] = g_mmax[idx];
    }
    __syncthreads();

    float4 part = make_float4(0.f, 0.f, 0.f, 0.f);  // ts, box, dfl, bce_tgt
    int cnt = min(g_cnt[b], LCAP);
    if (i < cnt) {
        int n = g_list[b][i];
        unsigned mk = g_mask[b * NTOT + n];
        float4 pb = g_pred[(size_t)b * NTOT + n];
        float x1 = pb.x, y1 = pb.y, x2 = pb.z, y2 = pb.w;
        float w1 = fmaxf(x2 - x1, 0.f), h1 = fmaxf(y2 - y1, 0.f);
        float a1 = w1 * h1;
        float best = -3.f; int bi = 0;
        unsigned mm = mk;
        while (mm) {
            int m = __ffs(mm) - 1; mm &= mm - 1;
            float v = iou_plain(x1, y1, x2, y2, a1,
                                sg[m][0], sg[m][1], sg[m][2], sg[m][3]);
            if (v > best) { best = v; bi = m; }
        }
        AInfo a = ainfo(b, n, p0, p1, p2);
        float zl = a.base[(size_t)(64 + sl[bi]) * a.hw];
        float alv = align_metric(zl, best);
        float score = fminf(fmaxf(alv / smm[bi] * best, 0.f), 1.f);
        part.x = score;
        if (score > 0.f) {
            float gx1 = sg[bi][0], gy1 = sg[bi][1];
            float gx2 = sg[bi][2], gy2 = sg[bi][3];
            float iw = fmaxf(fminf(x2, gx2) - fmaxf(x1, gx1), 0.f);
            float ih = fmaxf(fminf(y2, gy2) - fmaxf(y1, gy1), 0.f);
            float inter = iw * ih;
            float w2 = fmaxf(gx2 - gx1, 0.f), h2 = fmaxf(gy2 - gy1, 0.f);
            float uni = a1 + w2 * h2 - inter + 1e-7f;
            float iou = inter / uni;
            float dcx = (gx1 + gx2) * 0.5f - (x1 + x2) * 0.5f;
            float dcy = (gy1 + gy2) * 0.5f - (y1 + y2) * 0.5f;
            float rho2 = dcx * dcx + dcy * dcy;
            float cw = fmaxf(x2, gx2) - fminf(x1, gx1);
            float chh = fmaxf(y2, gy2) - fminf(y1, gy1);
            float c2 = cw * cw + chh * chh + 1e-7f;
            const float k4pi2 = 0.40528473456935108577f;
            float dv = atanf(w2 / (h2 + 1e-7f)) - atanf(w1 / (h1 + 1e-7f));
            float v = k4pi2 * dv * dv;
            float alpha = v / (1.f - iou + v + 1e-7f);
            float ciou = iou - (rho2 / c2 + alpha * v);
            part.y = (1.f - ciou) * score;
            float inv = 1.f / a.s;
            float tgt[4] = { (a.ax - gx1) * inv, (a.ay - gy1) * inv,
                             (gx2 - a.ax) * inv, (gy2 - a.ay) * inv };
            float dfl = 0.f;
            #pragma unroll
            for (int sd = 0; sd < 4; sd++) {
                float z[RMAX]; float mx = -3.4e38f;
                #pragma unroll
                for (int j = 0; j < RMAX; j++) {
                    z[j] = a.base[(size_t)(sd * RMAX + j) * a.hw];
                    mx = fmaxf(mx, z[j]);
                }
                float se = 0.f;
                #pragma unroll
                for (int j = 0; j < RMAX; j++) se += __expf(z[j] - mx);
                float ls = mx + __logf(se);
                float t = fminf(fmaxf(tgt[sd], 0.f), 15.f);
                int L = (int)floorf(t);
                int R = min(L + 1, RMAX - 1);
                float wl = (R == L) ? 1.f : ((float)R - t);
                float wr = (R == L) ? 0.f : (t - (float)L);
                dfl += (ls - z[L]) * wl + (ls - z[R]) * wr;
            }
            part.z = dfl * score;
            part.w = zl * score;
        }
    }
    float4 r = block_sum4_128(part);
    if (threadIdx.x == 0) {
        if (r.x != 0.f) atomicAdd(&g_acc[1], (double)r.x);
        if (r.y != 0.f) atomicAdd(&g_acc[2], (double)r.y);
        if (r.z != 0.f) atomicAdd(&g_acc[3], (double)r.z);
        if (r.w != 0.f) atomicAdd(&g_acc[4], (double)r.w);
        __threadfence();
        unsigned c = atomicAdd(&g_done, 1u);
        if (c == RTOT - 1) {
            double a0 = atomicAdd(&g_acc[0], 0.0);
            double a1 = atomicAdd(&g_acc[1], 0.0);
            double a2 = atomicAdd(&g_acc[2], 0.0);
            double a3 = atomicAdd(&g_acc[3], 0.0);
            double a4 = atomicAdd(&g_acc[4], 0.0);
            double tsum = a1 < 1.0 ? 1.0 : a1;
            out[0] = (float)((7.5 * a2 + 0.5 * (a0 - a4) + 1.5 * a3) / tsum);
            #pragma unroll
            for (int i2 = 0; i2 < 8; i2++) g_acc[i2] = 0.0;
            g_done = 0u;
        }
    }
}

// ---------------- launch -----------------------------------------------------
extern "C" void kernel_launch(void* const* d_in, const int* in_sizes, int n_in,
                              void* d_out, int out_size) {
    const float* p0  = (const float*)d_in[0];
    const float* p1  = (const float*)d_in[1];
    const float* p2  = (const float*)d_in[2];
    const float* gtb = (const float*)d_in[3];
    const int*   glw = (const int*)d_in[4];
    (void)in_sizes; (void)n_in; (void)out_size;

    k_decode<<<dim3(4 * DBLK, B_), 256>>>(p0, p1, p2);
    k_assign<<<dim3(M_, B_), 128>>>(p0, p1, p2, gtb, glw);
    k_resolve<<<dim3(RBLK, B_), 128>>>(p0, p1, p2, gtb, glw, (float*)d_out);
}